// round 3
// baseline (speedup 1.0000x reference)
#include <cuda_runtime.h>
#include <math.h>

// Problem constants
constexpr int NN = 50000;      // nodes
constexpr int NE = 800000;     // edges
constexpr int NG = 512;        // graphs
constexpr int F0 = 30;         // input features
constexpr int F1 = 256;        // hidden 1
constexpr int F2 = 128;        // hidden 2
constexpr int F3 = 64;         // hidden 3

// ---------------- scratch (device globals; no allocation allowed) ----------
constexpr size_t O_AGG0 = 0;                               // N x 30
constexpr size_t O_H1   = O_AGG0 + (size_t)NN * F0;        // N x 256
constexpr size_t O_T2   = O_H1   + (size_t)NN * F1;        // N x 128
constexpr size_t O_H2   = O_T2   + (size_t)NN * F2;        // N x 128
constexpr size_t O_T3   = O_H2   + (size_t)NN * F2;        // N x 64
constexpr size_t O_H3   = O_T3   + (size_t)NN * F3;        // N x 64
constexpr size_t SCRATCH_FLOATS = O_H3 + (size_t)NN * F3;

__device__ float g_scratch[SCRATCH_FLOATS];
__device__ int   g_deg[NN];
__device__ float g_dinv[NN];
__device__ int   g_rowptr[NN + 1];
__device__ int   g_cursor[NN];
__device__ int   g_col[NE];
__device__ float g_pool[NG * F3];
__device__ int   g_gstart[NG + 1];

// ---------------- small utility kernels -----------------------------------
__global__ void zero_kernel() {
    int i = blockIdx.x * blockDim.x + threadIdx.x;
    if (i < NN) { g_deg[i] = 0; g_cursor[i] = 0; }
    if (i < NG + 1) g_gstart[i] = NN;
}

__global__ void deg_kernel(const int* __restrict__ dst) {
    int e = blockIdx.x * blockDim.x + threadIdx.x;
    if (e < NE) atomicAdd(&g_deg[dst[e]], 1);
}

__global__ void dinv_kernel() {
    int i = blockIdx.x * blockDim.x + threadIdx.x;
    if (i < NN) g_dinv[i] = rsqrtf((float)(g_deg[i] + 1));  // +1 self-loop
}

// exclusive prefix sum of g_deg into g_rowptr (single block, shuffle scan)
__global__ void scan_kernel() {
    __shared__ int warpsum[32];
    __shared__ int carry_s;
    int t = threadIdx.x, lane = t & 31, w = t >> 5;
    if (t == 0) carry_s = 0;
    __syncthreads();
    for (int base = 0; base < NN; base += 1024) {
        int i = base + t;
        int v = (i < NN) ? g_deg[i] : 0;
        int x = v;
        #pragma unroll
        for (int off = 1; off < 32; off <<= 1) {
            int y = __shfl_up_sync(0xffffffffu, x, off);
            if (lane >= off) x += y;
        }
        if (lane == 31) warpsum[w] = x;
        __syncthreads();
        if (w == 0) {
            int s = warpsum[lane];
            #pragma unroll
            for (int off = 1; off < 32; off <<= 1) {
                int y = __shfl_up_sync(0xffffffffu, s, off);
                if (lane >= off) s += y;
            }
            warpsum[lane] = s;
        }
        __syncthreads();
        int excl = x - v + (w > 0 ? warpsum[w - 1] : 0) + carry_s;
        if (i < NN) g_rowptr[i] = excl;
        __syncthreads();                 // everyone done with carry_s
        if (t == 1023) carry_s = excl + v;
        __syncthreads();
    }
    if (t == 0) g_rowptr[NN] = carry_s;
}

__global__ void csr_fill_kernel(const int* __restrict__ src, const int* __restrict__ dst) {
    int e = blockIdx.x * blockDim.x + threadIdx.x;
    if (e < NE) {
        int d = dst[e];
        int p = atomicAdd(&g_cursor[d], 1);
        g_col[g_rowptr[d] + p] = src[e];
    }
}

// ---------------- aggregation: out[i] = sum_{s->i} dinv_s*dinv_i*X[s] + dinv_i^2*X[i]
// one warp per destination node; each lane owns VEC consecutive features
template <int F, int VEC, size_t XO, size_t OO>
__global__ void agg_kernel(const float* __restrict__ Xext,
                           const float* __restrict__ bias, int do_relu) {
    int warp = (blockIdx.x * blockDim.x + threadIdx.x) >> 5;
    int lane = threadIdx.x & 31;
    if (warp >= NN) return;
    constexpr int NV = F / VEC;  // active lanes

    const float* X = Xext ? Xext : (g_scratch + XO);
    float* out = g_scratch + OO;

    float acc[VEC];
    #pragma unroll
    for (int v = 0; v < VEC; v++) acc[v] = 0.0f;

    float di = g_dinv[warp];
    int b = g_rowptr[warp];
    int e = g_rowptr[warp + 1];

    if (lane < NV) {  // self-loop term
        float w = di * di;
        const float* xr = X + (size_t)warp * F + lane * VEC;
        if (VEC == 4) {
            float4 xv = *(const float4*)xr;
            acc[0] += w * xv.x; acc[1] += w * xv.y; acc[2] += w * xv.z; acc[3] += w * xv.w;
        } else if (VEC == 2) {
            float2 xv = *(const float2*)xr;
            acc[0] += w * xv.x; acc[1] += w * xv.y;
        } else {
            acc[0] += w * xr[0];
        }
    }
    // software-pipelined edge loop (prefetch col + dinv)
    int sNext = (b < e) ? g_col[b] : 0;
    float dNext = (b < e) ? g_dinv[sNext] : 0.0f;
    for (int j = b; j < e; j++) {
        int s = sNext;
        float ds = dNext;
        int jn = j + 1;
        if (jn < e) { sNext = g_col[jn]; dNext = g_dinv[sNext]; }
        float w = di * ds;
        if (lane < NV) {
            const float* xr = X + (size_t)s * F + lane * VEC;
            if (VEC == 4) {
                float4 xv = *(const float4*)xr;
                acc[0] += w * xv.x; acc[1] += w * xv.y; acc[2] += w * xv.z; acc[3] += w * xv.w;
            } else if (VEC == 2) {
                float2 xv = *(const float2*)xr;
                acc[0] += w * xv.x; acc[1] += w * xv.y;
            } else {
                acc[0] += w * xr[0];
            }
        }
    }
    if (lane < NV) {
        #pragma unroll
        for (int v = 0; v < VEC; v++) {
            float r = acc[v] + (bias ? bias[lane * VEC + v] : 0.0f);
            if (do_relu) r = fmaxf(r, 0.0f);
            acc[v] = r;
        }
        float* o = out + (size_t)warp * F + lane * VEC;
        if (VEC == 4)      *(float4*)o = make_float4(acc[0], acc[1], acc[2], acc[3]);
        else if (VEC == 2) *(float2*)o = make_float2(acc[0], acc[1]);
        else               o[0] = acc[0];
    }
}

// ---------------- SGEMM 128x128, 8x8 microtile ------------------------------
// C[M,N] = A[M,K] @ B[K,N] (+bias, relu). 256 threads (16x16).
// Per k-step/thread: 8 broadcast LDS (a) + 2 LDS.128 (b) + 64 FFMA -> FMA-bound.
// K arbitrary (guarded loads). N must be a multiple of 128.
template <size_t AO, size_t CO, bool BIAS_RELU>
__global__ void sgemm128_kernel(const float* __restrict__ B,
                                const float* __restrict__ bias,
                                int M, int N, int K) {
    constexpr int BM = 128, BN = 128, BK = 16;
    __shared__ float sA[BM][BK + 1];   // row-major, +1 pad
    __shared__ float sB[BK][BN];
    const float* A = g_scratch + AO;
    float* C = g_scratch + CO;

    int t = threadIdx.x;
    int tx = t % 16, ty = t / 16;
    int rowBase = blockIdx.y * BM;
    int colBase = blockIdx.x * BN;

    float acc[8][8] = {};  // rows ty*8+m ; cols tx*4+n (n<4), 64+tx*4+(n-4)

    int nk = (K + BK - 1) / BK;
    for (int kt = 0; kt < nk; kt++) {
        int k0 = kt * BK;
        // load A tile [BM x BK]: 8 scalars/thread, coalesced (16 thr per row)
        #pragma unroll
        for (int i = 0; i < 8; i++) {
            int id = t + i * 256;
            int r = id / BK, c = id % BK;
            int gr = rowBase + r;
            sA[r][c] = (gr < M && k0 + c < K) ? A[(size_t)gr * K + k0 + c] : 0.0f;
        }
        // load B tile [BK x BN]: 8 scalars/thread, coalesced
        #pragma unroll
        for (int i = 0; i < 8; i++) {
            int id = t + i * 256;
            int r = id / BN, c = id % BN;
            sB[r][c] = (k0 + r < K) ? B[(size_t)(k0 + r) * N + colBase + c] : 0.0f;
        }
        __syncthreads();
        #pragma unroll
        for (int k = 0; k < BK; k++) {
            float a[8];
            #pragma unroll
            for (int m = 0; m < 8; m++) a[m] = sA[ty * 8 + m][k];   // broadcast
            float4 b0 = *(const float4*)&sB[k][tx * 4];             // LDS.128
            float4 b1 = *(const float4*)&sB[k][64 + tx * 4];        // LDS.128
            float b[8] = {b0.x, b0.y, b0.z, b0.w, b1.x, b1.y, b1.z, b1.w};
            #pragma unroll
            for (int m = 0; m < 8; m++)
                #pragma unroll
                for (int n = 0; n < 8; n++) acc[m][n] += a[m] * b[n];
        }
        __syncthreads();
    }

    float bv[8];
    if (BIAS_RELU) {
        #pragma unroll
        for (int n = 0; n < 4; n++) bv[n] = bias[colBase + tx * 4 + n];
        #pragma unroll
        for (int n = 0; n < 4; n++) bv[4 + n] = bias[colBase + 64 + tx * 4 + n];
    }
    #pragma unroll
    for (int m = 0; m < 8; m++) {
        int r = rowBase + ty * 8 + m;
        if (r < M) {
            float v[8];
            #pragma unroll
            for (int n = 0; n < 8; n++) {
                v[n] = acc[m][n];
                if (BIAS_RELU) v[n] = fmaxf(v[n] + bv[n], 0.0f);
            }
            *(float4*)&C[(size_t)r * N + colBase + tx * 4] =
                make_float4(v[0], v[1], v[2], v[3]);
            *(float4*)&C[(size_t)r * N + colBase + 64 + tx * 4] =
                make_float4(v[4], v[5], v[6], v[7]);
        }
    }
}

// ---------------- SGEMM 128x64 (for N=64 layer-3) ---------------------------
template <size_t AO, size_t CO>
__global__ void sgemm_kernel(const float* __restrict__ B, int M, int N, int K) {
    constexpr int BM = 128, BN = 64, BK = 16, TM = 8, TN = 4;
    __shared__ float sA[BM][BK + 1];
    __shared__ float sB[BK][BN];
    const float* A = g_scratch + AO;
    float* C = g_scratch + CO;

    int t = threadIdx.x;
    int tx = t % 16, ty = t / 16;
    int rowBase = blockIdx.y * BM;
    int colBase = blockIdx.x * BN;

    float acc[TM][TN] = {};
    for (int k0 = 0; k0 < K; k0 += BK) {
        #pragma unroll
        for (int i = 0; i < 8; i++) {
            int id = t + i * 256;
            int r = id / BK, c = id % BK;
            int gr = rowBase + r;
            sA[r][c] = (gr < M) ? A[(size_t)gr * K + k0 + c] : 0.0f;
        }
        #pragma unroll
        for (int i = 0; i < 4; i++) {
            int id = t + i * 256;
            int r = id / BN, c = id % BN;
            sB[r][c] = B[(size_t)(k0 + r) * N + colBase + c];
        }
        __syncthreads();
        #pragma unroll
        for (int k = 0; k < BK; k++) {
            float a[TM];
            #pragma unroll
            for (int m = 0; m < TM; m++) a[m] = sA[ty * TM + m][k];
            float4 bvv = *(const float4*)&sB[k][tx * TN];
            float b[TN] = {bvv.x, bvv.y, bvv.z, bvv.w};
            #pragma unroll
            for (int m = 0; m < TM; m++)
                #pragma unroll
                for (int n = 0; n < TN; n++) acc[m][n] += a[m] * b[n];
        }
        __syncthreads();
    }
    #pragma unroll
    for (int m = 0; m < TM; m++) {
        int r = rowBase + ty * TM + m;
        if (r < M) {
            float4 v = make_float4(acc[m][0], acc[m][1], acc[m][2], acc[m][3]);
            *(float4*)&C[(size_t)r * N + colBase + tx * TN] = v;
        }
    }
}

// ---------------- pooling (batch is SORTED -> per-graph ranges) -------------
__global__ void gstart_kernel(const int* __restrict__ batch) {
    int i = blockIdx.x * blockDim.x + threadIdx.x;
    if (i < NN) atomicMin(&g_gstart[batch[i]], i);
}

// suffix-min over g_gstart so empty graphs inherit the next start (one block)
__global__ void gstart_fix_kernel() {
    __shared__ int s[NG + 1];
    int t = threadIdx.x;  // 512 threads
    s[t] = g_gstart[t];
    if (t == 0) s[NG] = NN;
    __syncthreads();
    for (int off = 1; off <= NG; off <<= 1) {
        int v = (t + off <= NG) ? s[t + off] : NN;
        __syncthreads();
        s[t] = min(s[t], v);
        __syncthreads();
    }
    g_gstart[t] = s[t];
    if (t == 0) g_gstart[NG] = NN;
}

__global__ void pool_kernel() {  // one block per graph, 256 threads
    int g = blockIdx.x;
    int beg = g_gstart[g], end = g_gstart[g + 1];
    int sub = threadIdx.x >> 6, f = threadIdx.x & 63;
    float acc = 0.0f;
    for (int i = beg + sub; i < end; i += 4)
        acc += g_scratch[O_H3 + (size_t)i * F3 + f];
    __shared__ float red[256];
    red[threadIdx.x] = acc;
    __syncthreads();
    if (sub == 0)
        g_pool[g * F3 + f] = red[f] + red[64 + f] + red[128 + f] + red[192 + f];
}

// ---------------- head: logits, sigmoid, BCE loss ---------------------------
__global__ void final_kernel(const float* __restrict__ Wl, const float* __restrict__ bl,
                             const int* __restrict__ targets, float* __restrict__ out) {
    __shared__ float red[NG];
    int g = threadIdx.x;
    float c = fmaxf((float)(g_gstart[g + 1] - g_gstart[g]), 1.0f);
    float z = bl[0];
    #pragma unroll
    for (int f = 0; f < F3; f++) z += (g_pool[g * F3 + f] / c) * Wl[f];
    out[g] = 1.0f / (1.0f + expf(-z));
    float y = (float)targets[g];
    red[g] = fmaxf(z, 0.0f) + log1pf(expf(-fabsf(z))) - z * y;
    __syncthreads();
    for (int s = NG / 2; s > 0; s >>= 1) {
        if (g < s) red[g] += red[g + s];
        __syncthreads();
    }
    if (g == 0) out[NG] = red[0] / (float)NG;
}

// ---------------- launch ----------------------------------------------------
extern "C" void kernel_launch(void* const* d_in, const int* in_sizes, int n_in,
                              void* d_out, int out_size) {
    const float* x       = (const float*)d_in[0];   // [N,30]
    const int*   eidx    = (const int*)d_in[1];     // [2,E]
    const int*   batch   = (const int*)d_in[2];     // [N] sorted
    const int*   targets = (const int*)d_in[3];     // [G]
    const float* W1 = (const float*)d_in[4];
    const float* b1 = (const float*)d_in[5];
    const float* W2 = (const float*)d_in[6];
    const float* b2 = (const float*)d_in[7];
    const float* W3 = (const float*)d_in[8];
    const float* b3 = (const float*)d_in[9];
    const float* Wl = (const float*)d_in[10];
    const float* bl = (const float*)d_in[11];
    float* out = (float*)d_out;

    const int* src = eidx;       // edge_index[0]
    const int* dst = eidx + NE;  // edge_index[1]

    const int TB = 256;
    int nb_nodes = (NN + TB - 1) / TB;
    int nb_edges = (NE + TB - 1) / TB;

    // graph preprocessing (recomputed every call; deterministic)
    zero_kernel<<<nb_nodes, TB>>>();
    deg_kernel<<<nb_edges, TB>>>(dst);
    dinv_kernel<<<nb_nodes, TB>>>();
    scan_kernel<<<1, 1024>>>();
    csr_fill_kernel<<<nb_edges, TB>>>(src, dst);
    gstart_kernel<<<nb_nodes, TB>>>(batch);
    gstart_fix_kernel<<<1, NG>>>();

    int agg_blocks = (NN * 32 + TB - 1) / TB;  // one warp per node
    int mRows = (NN + 127) / 128;

    // layer 1: aggregate 30-dim input, then GEMM 30->256 (+b1, relu)
    agg_kernel<F0, 1, 0, O_AGG0><<<agg_blocks, TB>>>(x, nullptr, 0);
    {
        dim3 grid(F1 / 128, mRows);
        sgemm128_kernel<O_AGG0, O_H1, true><<<grid, 256>>>(W1, b1, NN, F1, F0);
    }

    // layer 2: GEMM 256->128, aggregate, +b2, relu
    {
        dim3 grid(F2 / 128, mRows);
        sgemm128_kernel<O_H1, O_T2, false><<<grid, 256>>>(W2, nullptr, NN, F2, F1);
    }
    agg_kernel<F2, 4, O_T2, O_H2><<<agg_blocks, TB>>>(nullptr, b2, 1);

    // layer 3: GEMM 128->64, aggregate, +b3 (no relu)
    {
        dim3 grid(F3 / 64, mRows);
        sgemm_kernel<O_H2, O_T3><<<grid, 256>>>(W3, NN, F3, F2);
    }
    agg_kernel<F3, 2, O_T3, O_H3><<<agg_blocks, TB>>>(nullptr, b3, 0);

    // global mean pool + head
    pool_kernel<<<NG, 256>>>();
    final_kernel<<<1, NG>>>(Wl, bl, targets, out);
    (void)in_sizes; (void)n_in; (void)out_size;
}

// round 5
// speedup vs baseline: 1.0769x; 1.0769x over previous
#include <cuda_runtime.h>
#include <math.h>

// Problem constants
constexpr int NN = 50000;      // nodes
constexpr int NE = 800000;     // edges
constexpr int NG = 512;        // graphs
constexpr int F0 = 30;         // input features
constexpr int F1 = 256;        // hidden 1
constexpr int F2 = 128;        // hidden 2
constexpr int F3 = 64;         // hidden 3

// ---------------- scratch (device globals; no allocation allowed) ----------
constexpr size_t O_AGG0 = 0;                               // N x 30
constexpr size_t O_H1   = O_AGG0 + (size_t)NN * F0;        // N x 256
constexpr size_t O_T2   = O_H1   + (size_t)NN * F1;        // N x 128
constexpr size_t O_H2   = O_T2   + (size_t)NN * F2;        // N x 128
constexpr size_t O_T3   = O_H2   + (size_t)NN * F2;        // N x 64
constexpr size_t O_H3   = O_T3   + (size_t)NN * F3;        // N x 64
constexpr size_t SCRATCH_FLOATS = O_H3 + (size_t)NN * F3;

constexpr int SCAN_CHUNK = 1024;
constexpr int SCAN_NB = (NN + SCAN_CHUNK - 1) / SCAN_CHUNK;  // 49

__device__ float g_scratch[SCRATCH_FLOATS];
__device__ int   g_deg[NN];
__device__ float g_dinv[NN];
__device__ int   g_rowptr[NN + 1];
__device__ int   g_cursor[NN];
__device__ int   g_col[NE];
__device__ float g_pool[NG * F3];
__device__ int   g_gstart[NG + 1];
__device__ int   g_blocksum[SCAN_NB];
__device__ int   g_blockoff[SCAN_NB];

// ---------------- small utility kernels -----------------------------------
__global__ void zero_kernel() {
    int i = blockIdx.x * blockDim.x + threadIdx.x;
    if (i < NN) { g_deg[i] = 0; g_cursor[i] = 0; }
    if (i < NG + 1) g_gstart[i] = NN;
}

// 4 edges per thread via int4 (NE % 4 == 0; dst half is 16B-aligned)
__global__ void deg_kernel(const int* __restrict__ dst) {
    int e4 = blockIdx.x * blockDim.x + threadIdx.x;
    if (e4 < NE / 4) {
        int4 d = ((const int4*)dst)[e4];
        atomicAdd(&g_deg[d.x], 1);
        atomicAdd(&g_deg[d.y], 1);
        atomicAdd(&g_deg[d.z], 1);
        atomicAdd(&g_deg[d.w], 1);
    }
}

// ---------------- parallel exclusive scan of g_deg -> g_rowptr --------------
// phase 1: per-block local exclusive scan (1024 elems/block), store block sum.
// Also computes g_dinv (fused; reads g_deg anyway).
__global__ void scan_local_kernel() {
    __shared__ int warpsum[32];
    int blk = blockIdx.x;
    int t = threadIdx.x, lane = t & 31, w = t >> 5;
    int i = blk * SCAN_CHUNK + t;
    int v = (i < NN) ? g_deg[i] : 0;
    if (i < NN) g_dinv[i] = rsqrtf((float)(v + 1));  // +1 self-loop
    int x = v;
    #pragma unroll
    for (int off = 1; off < 32; off <<= 1) {
        int y = __shfl_up_sync(0xffffffffu, x, off);
        if (lane >= off) x += y;
    }
    if (lane == 31) warpsum[w] = x;
    __syncthreads();
    if (w == 0) {
        int s = warpsum[lane];
        #pragma unroll
        for (int off = 1; off < 32; off <<= 1) {
            int y = __shfl_up_sync(0xffffffffu, s, off);
            if (lane >= off) s += y;
        }
        warpsum[lane] = s;
    }
    __syncthreads();
    int excl = x - v + (w > 0 ? warpsum[w - 1] : 0);
    if (i < NN) g_rowptr[i] = excl;               // local exclusive
    if (t == SCAN_CHUNK - 1) g_blocksum[blk] = excl + v;
}

// phase 2: one block scans the SCAN_NB block sums (exclusive) + total
__global__ void scan_block_kernel() {
    __shared__ int warpsum[32];
    int t = threadIdx.x, lane = t & 31, w = t >> 5;   // 64 threads, 2 warps
    int v = (t < SCAN_NB) ? g_blocksum[t] : 0;
    int x = v;
    #pragma unroll
    for (int off = 1; off < 32; off <<= 1) {
        int y = __shfl_up_sync(0xffffffffu, x, off);
        if (lane >= off) x += y;
    }
    if (lane == 31) warpsum[w] = x;
    __syncthreads();
    int excl = x - v + (w > 0 ? warpsum[0] : 0);
    if (t < SCAN_NB) g_blockoff[t] = excl;
    if (t == SCAN_NB - 1) g_rowptr[NN] = excl + v;  // grand total
}

// phase 3: add block offsets
__global__ void scan_add_kernel() {
    int i = blockIdx.x * blockDim.x + threadIdx.x;
    if (i < NN) g_rowptr[i] += g_blockoff[i >> 10];
}

// 4 edges per thread via int4
__global__ void csr_fill_kernel(const int* __restrict__ src, const int* __restrict__ dst) {
    int e4 = blockIdx.x * blockDim.x + threadIdx.x;
    if (e4 < NE / 4) {
        int4 s = ((const int4*)src)[e4];
        int4 d = ((const int4*)dst)[e4];
        int p;
        p = atomicAdd(&g_cursor[d.x], 1); g_col[g_rowptr[d.x] + p] = s.x;
        p = atomicAdd(&g_cursor[d.y], 1); g_col[g_rowptr[d.y] + p] = s.y;
        p = atomicAdd(&g_cursor[d.z], 1); g_col[g_rowptr[d.z] + p] = s.z;
        p = atomicAdd(&g_cursor[d.w], 1); g_col[g_rowptr[d.w] + p] = s.w;
    }
}

// ---------------- aggregation: out[i] = sum_{s->i} dinv_s*dinv_i*X[s] + dinv_i^2*X[i]
// one warp per destination node; each lane owns VEC consecutive features
template <int F, int VEC, size_t XO, size_t OO>
__global__ void agg_kernel(const float* __restrict__ Xext,
                           const float* __restrict__ bias, int do_relu) {
    int warp = (blockIdx.x * blockDim.x + threadIdx.x) >> 5;
    int lane = threadIdx.x & 31;
    if (warp >= NN) return;
    constexpr int NV = F / VEC;  // active lanes

    const float* X = Xext ? Xext : (g_scratch + XO);
    float* out = g_scratch + OO;

    float acc[VEC];
    #pragma unroll
    for (int v = 0; v < VEC; v++) acc[v] = 0.0f;

    float di = g_dinv[warp];
    int b = g_rowptr[warp];
    int e = g_rowptr[warp + 1];

    if (lane < NV) {  // self-loop term
        float w = di * di;
        const float* xr = X + (size_t)warp * F + lane * VEC;
        if (VEC == 4) {
            float4 xv = *(const float4*)xr;
            acc[0] += w * xv.x; acc[1] += w * xv.y; acc[2] += w * xv.z; acc[3] += w * xv.w;
        } else if (VEC == 2) {
            float2 xv = *(const float2*)xr;
            acc[0] += w * xv.x; acc[1] += w * xv.y;
        } else {
            acc[0] += w * xr[0];
        }
    }
    // software-pipelined edge loop (prefetch col + dinv)
    int sNext = (b < e) ? g_col[b] : 0;
    float dNext = (b < e) ? g_dinv[sNext] : 0.0f;
    for (int j = b; j < e; j++) {
        int s = sNext;
        float ds = dNext;
        int jn = j + 1;
        if (jn < e) { sNext = g_col[jn]; dNext = g_dinv[sNext]; }
        float w = di * ds;
        if (lane < NV) {
            const float* xr = X + (size_t)s * F + lane * VEC;
            if (VEC == 4) {
                float4 xv = *(const float4*)xr;
                acc[0] += w * xv.x; acc[1] += w * xv.y; acc[2] += w * xv.z; acc[3] += w * xv.w;
            } else if (VEC == 2) {
                float2 xv = *(const float2*)xr;
                acc[0] += w * xv.x; acc[1] += w * xv.y;
            } else {
                acc[0] += w * xr[0];
            }
        }
    }
    if (lane < NV) {
        #pragma unroll
        for (int v = 0; v < VEC; v++) {
            float r = acc[v] + (bias ? bias[lane * VEC + v] : 0.0f);
            if (do_relu) r = fmaxf(r, 0.0f);
            acc[v] = r;
        }
        float* o = out + (size_t)warp * F + lane * VEC;
        if (VEC == 4)      *(float4*)o = make_float4(acc[0], acc[1], acc[2], acc[3]);
        else if (VEC == 2) *(float2*)o = make_float2(acc[0], acc[1]);
        else               o[0] = acc[0];
    }
}

// ---------------- SGEMM 128x128, 8x8 microtile ------------------------------
// C[M,N] = A[M,K] @ B[K,N] (+bias, relu). 256 threads (16x16).
// Per k-step/thread: 8 broadcast LDS (a) + 2 LDS.128 (b) + 64 FFMA -> FMA-bound.
// K arbitrary (guarded loads). N must be a multiple of 128.
template <size_t AO, size_t CO, bool BIAS_RELU>
__global__ void sgemm128_kernel(const float* __restrict__ B,
                                const float* __restrict__ bias,
                                int M, int N, int K) {
    constexpr int BM = 128, BN = 128, BK = 16;
    __shared__ float sA[BM][BK + 1];   // row-major, +1 pad
    __shared__ float sB[BK][BN];
    const float* A = g_scratch + AO;
    float* C = g_scratch + CO;

    int t = threadIdx.x;
    int tx = t % 16, ty = t / 16;
    int rowBase = blockIdx.y * BM;
    int colBase = blockIdx.x * BN;

    float acc[8][8] = {};  // rows ty*8+m ; cols tx*4+n (n<4), 64+tx*4+(n-4)

    int nk = (K + BK - 1) / BK;
    for (int kt = 0; kt < nk; kt++) {
        int k0 = kt * BK;
        // load A tile [BM x BK]: 8 scalars/thread, coalesced (16 thr per row)
        #pragma unroll
        for (int i = 0; i < 8; i++) {
            int id = t + i * 256;
            int r = id / BK, c = id % BK;
            int gr = rowBase + r;
            sA[r][c] = (gr < M && k0 + c < K) ? A[(size_t)gr * K + k0 + c] : 0.0f;
        }
        // load B tile [BK x BN]: 8 scalars/thread, coalesced
        #pragma unroll
        for (int i = 0; i < 8; i++) {
            int id = t + i * 256;
            int r = id / BN, c = id % BN;
            sB[r][c] = (k0 + r < K) ? B[(size_t)(k0 + r) * N + colBase + c] : 0.0f;
        }
        __syncthreads();
        #pragma unroll
        for (int k = 0; k < BK; k++) {
            float a[8];
            #pragma unroll
            for (int m = 0; m < 8; m++) a[m] = sA[ty * 8 + m][k];   // broadcast
            float4 b0 = *(const float4*)&sB[k][tx * 4];             // LDS.128
            float4 b1 = *(const float4*)&sB[k][64 + tx * 4];        // LDS.128
            float b[8] = {b0.x, b0.y, b0.z, b0.w, b1.x, b1.y, b1.z, b1.w};
            #pragma unroll
            for (int m = 0; m < 8; m++)
                #pragma unroll
                for (int n = 0; n < 8; n++) acc[m][n] += a[m] * b[n];
        }
        __syncthreads();
    }

    float bv[8];
    if (BIAS_RELU) {
        #pragma unroll
        for (int n = 0; n < 4; n++) bv[n] = bias[colBase + tx * 4 + n];
        #pragma unroll
        for (int n = 0; n < 4; n++) bv[4 + n] = bias[colBase + 64 + tx * 4 + n];
    }
    #pragma unroll
    for (int m = 0; m < 8; m++) {
        int r = rowBase + ty * 8 + m;
        if (r < M) {
            float v[8];
            #pragma unroll
            for (int n = 0; n < 8; n++) {
                v[n] = acc[m][n];
                if (BIAS_RELU) v[n] = fmaxf(v[n] + bv[n], 0.0f);
            }
            *(float4*)&C[(size_t)r * N + colBase + tx * 4] =
                make_float4(v[0], v[1], v[2], v[3]);
            *(float4*)&C[(size_t)r * N + colBase + 64 + tx * 4] =
                make_float4(v[4], v[5], v[6], v[7]);
        }
    }
}

// ---------------- SGEMM 128x64 (for N=64 layer-3) ---------------------------
template <size_t AO, size_t CO>
__global__ void sgemm_kernel(const float* __restrict__ B, int M, int N, int K) {
    constexpr int BM = 128, BN = 64, BK = 16, TM = 8, TN = 4;
    __shared__ float sA[BM][BK + 1];
    __shared__ float sB[BK][BN];
    const float* A = g_scratch + AO;
    float* C = g_scratch + CO;

    int t = threadIdx.x;
    int tx = t % 16, ty = t / 16;
    int rowBase = blockIdx.y * BM;
    int colBase = blockIdx.x * BN;

    float acc[TM][TN] = {};
    for (int k0 = 0; k0 < K; k0 += BK) {
        #pragma unroll
        for (int i = 0; i < 8; i++) {
            int id = t + i * 256;
            int r = id / BK, c = id % BK;
            int gr = rowBase + r;
            sA[r][c] = (gr < M) ? A[(size_t)gr * K + k0 + c] : 0.0f;
        }
        #pragma unroll
        for (int i = 0; i < 4; i++) {
            int id = t + i * 256;
            int r = id / BN, c = id % BN;
            sB[r][c] = B[(size_t)(k0 + r) * N + colBase + c];
        }
        __syncthreads();
        #pragma unroll
        for (int k = 0; k < BK; k++) {
            float a[TM];
            #pragma unroll
            for (int m = 0; m < TM; m++) a[m] = sA[ty * TM + m][k];
            float4 bvv = *(const float4*)&sB[k][tx * TN];
            float b[TN] = {bvv.x, bvv.y, bvv.z, bvv.w};
            #pragma unroll
            for (int m = 0; m < TM; m++)
                #pragma unroll
                for (int n = 0; n < TN; n++) acc[m][n] += a[m] * b[n];
        }
        __syncthreads();
    }
    #pragma unroll
    for (int m = 0; m < TM; m++) {
        int r = rowBase + ty * TM + m;
        if (r < M) {
            float4 v = make_float4(acc[m][0], acc[m][1], acc[m][2], acc[m][3]);
            *(float4*)&C[(size_t)r * N + colBase + tx * TN] = v;
        }
    }
}

// ---------------- pooling (batch is SORTED -> per-graph ranges) -------------
__global__ void gstart_kernel(const int* __restrict__ batch) {
    int i = blockIdx.x * blockDim.x + threadIdx.x;
    if (i < NN) atomicMin(&g_gstart[batch[i]], i);
}

// suffix-min over g_gstart so empty graphs inherit the next start (one block)
__global__ void gstart_fix_kernel() {
    __shared__ int s[NG + 1];
    int t = threadIdx.x;  // 512 threads
    s[t] = g_gstart[t];
    if (t == 0) s[NG] = NN;
    __syncthreads();
    for (int off = 1; off <= NG; off <<= 1) {
        int v = (t + off <= NG) ? s[t + off] : NN;
        __syncthreads();
        s[t] = min(s[t], v);
        __syncthreads();
    }
    g_gstart[t] = s[t];
    if (t == 0) g_gstart[NG] = NN;
}

__global__ void pool_kernel() {  // one block per graph, 256 threads
    int g = blockIdx.x;
    int beg = g_gstart[g], end = g_gstart[g + 1];
    int sub = threadIdx.x >> 6, f = threadIdx.x & 63;
    float acc = 0.0f;
    for (int i = beg + sub; i < end; i += 4)
        acc += g_scratch[O_H3 + (size_t)i * F3 + f];
    __shared__ float red[256];
    red[threadIdx.x] = acc;
    __syncthreads();
    if (sub == 0)
        g_pool[g * F3 + f] = red[f] + red[64 + f] + red[128 + f] + red[192 + f];
}

// ---------------- head: logits, sigmoid, BCE loss ---------------------------
__global__ void final_kernel(const float* __restrict__ Wl, const float* __restrict__ bl,
                             const int* __restrict__ targets, float* __restrict__ out) {
    __shared__ float red[NG];
    int g = threadIdx.x;
    float c = fmaxf((float)(g_gstart[g + 1] - g_gstart[g]), 1.0f);
    float z = bl[0];
    #pragma unroll
    for (int f = 0; f < F3; f++) z += (g_pool[g * F3 + f] / c) * Wl[f];
    out[g] = 1.0f / (1.0f + expf(-z));
    float y = (float)targets[g];
    red[g] = fmaxf(z, 0.0f) + log1pf(expf(-fabsf(z))) - z * y;
    __syncthreads();
    for (int s = NG / 2; s > 0; s >>= 1) {
        if (g < s) red[g] += red[g + s];
        __syncthreads();
    }
    if (g == 0) out[NG] = red[0] / (float)NG;
}

// ---------------- launch ----------------------------------------------------
extern "C" void kernel_launch(void* const* d_in, const int* in_sizes, int n_in,
                              void* d_out, int out_size) {
    const float* x       = (const float*)d_in[0];   // [N,30]
    const int*   eidx    = (const int*)d_in[1];     // [2,E]
    const int*   batch   = (const int*)d_in[2];     // [N] sorted
    const int*   targets = (const int*)d_in[3];     // [G]
    const float* W1 = (const float*)d_in[4];
    const float* b1 = (const float*)d_in[5];
    const float* W2 = (const float*)d_in[6];
    const float* b2 = (const float*)d_in[7];
    const float* W3 = (const float*)d_in[8];
    const float* b3 = (const float*)d_in[9];
    const float* Wl = (const float*)d_in[10];
    const float* bl = (const float*)d_in[11];
    float* out = (float*)d_out;

    const int* src = eidx;       // edge_index[0]
    const int* dst = eidx + NE;  // edge_index[1]

    const int TB = 256;
    int nb_nodes = (NN + TB - 1) / TB;
    int nb_edges4 = (NE / 4 + TB - 1) / TB;

    // graph preprocessing (recomputed every call; deterministic)
    zero_kernel<<<nb_nodes, TB>>>();
    deg_kernel<<<nb_edges4, TB>>>(dst);
    scan_local_kernel<<<SCAN_NB, SCAN_CHUNK>>>();   // also writes g_dinv
    scan_block_kernel<<<1, 64>>>();
    scan_add_kernel<<<nb_nodes, TB>>>();
    csr_fill_kernel<<<nb_edges4, TB>>>(src, dst);
    gstart_kernel<<<nb_nodes, TB>>>(batch);
    gstart_fix_kernel<<<1, NG>>>();

    int agg_blocks = (NN * 32 + TB - 1) / TB;  // one warp per node
    int mRows = (NN + 127) / 128;

    // layer 1: aggregate 30-dim input, then GEMM 30->256 (+b1, relu)
    agg_kernel<F0, 1, 0, O_AGG0><<<agg_blocks, TB>>>(x, nullptr, 0);
    {
        dim3 grid(F1 / 128, mRows);
        sgemm128_kernel<O_AGG0, O_H1, true><<<grid, 256>>>(W1, b1, NN, F1, F0);
    }

    // layer 2: GEMM 256->128, aggregate, +b2, relu
    {
        dim3 grid(F2 / 128, mRows);
        sgemm128_kernel<O_H1, O_T2, false><<<grid, 256>>>(W2, nullptr, NN, F2, F1);
    }
    agg_kernel<F2, 4, O_T2, O_H2><<<agg_blocks, TB>>>(nullptr, b2, 1);

    // layer 3: GEMM 128->64, aggregate, +b3 (no relu)
    {
        dim3 grid(F3 / 64, mRows);
        sgemm_kernel<O_H2, O_T3><<<grid, 256>>>(W3, NN, F3, F2);
    }
    agg_kernel<F3, 2, O_T3, O_H3><<<agg_blocks, TB>>>(nullptr, b3, 0);

    // global mean pool + head
    pool_kernel<<<NG, 256>>>();
    final_kernel<<<1, NG>>>(Wl, bl, targets, out);
    (void)in_sizes; (void)n_in; (void)out_size;
}

// round 13
// speedup vs baseline: 1.1927x; 1.1075x over previous
#include <cuda_runtime.h>
#include <cuda_bf16.h>
#include <stdint.h>
#include <math.h>

// Problem constants
constexpr int NN = 50000;      // nodes
constexpr int NE = 800000;     // edges
constexpr int NG = 512;        // graphs
constexpr int F0 = 30;         // input features
constexpr int F1 = 256;        // hidden 1
constexpr int F2 = 128;        // hidden 2
constexpr int F3 = 64;         // hidden 3

// ---------------- scratch (device globals; no allocation allowed) ----------
constexpr size_t O_AGG0 = 0;                               // N x 30
constexpr size_t O_H1   = O_AGG0 + (size_t)NN * F0;        // N x 256
constexpr size_t O_T2   = O_H1   + (size_t)NN * F1;        // N x 128
constexpr size_t O_H2   = O_T2   + (size_t)NN * F2;        // N x 128
constexpr size_t O_T3   = O_H2   + (size_t)NN * F2;        // N x 64
constexpr size_t O_H3   = O_T3   + (size_t)NN * F3;        // N x 64
constexpr size_t SCRATCH_FLOATS = O_H3 + (size_t)NN * F3;

constexpr int SCAN_CHUNK = 1024;
constexpr int SCAN_NB = (NN + SCAN_CHUNK - 1) / SCAN_CHUNK;  // 49

__device__ float g_scratch[SCRATCH_FLOATS];
__device__ int   g_deg[NN];
__device__ float g_dinv[NN];
__device__ int   g_rowptr[NN + 1];
__device__ int   g_cursor[NN];
__device__ int   g_col[NE];
__device__ float g_pool[NG * F3];
__device__ int   g_gstart[NG + 1];
__device__ int   g_blocksum[SCAN_NB];
__device__ int   g_blockoff[SCAN_NB];

// ---------------- small utility kernels -----------------------------------
__global__ void zero_kernel() {
    int i = blockIdx.x * blockDim.x + threadIdx.x;
    if (i < NN) { g_deg[i] = 0; g_cursor[i] = 0; }
}

// 4 edges per thread via int4 (NE % 4 == 0; dst half is 16B-aligned)
__global__ void deg_kernel(const int* __restrict__ dst) {
    int e4 = blockIdx.x * blockDim.x + threadIdx.x;
    if (e4 < NE / 4) {
        int4 d = ((const int4*)dst)[e4];
        atomicAdd(&g_deg[d.x], 1);
        atomicAdd(&g_deg[d.y], 1);
        atomicAdd(&g_deg[d.z], 1);
        atomicAdd(&g_deg[d.w], 1);
    }
}

// ---------------- parallel exclusive scan of g_deg -> g_rowptr --------------
// phase 1: per-block local exclusive scan; also computes g_dinv (fused).
__global__ void scan_local_kernel() {
    __shared__ int warpsum[32];
    int blk = blockIdx.x;
    int t = threadIdx.x, lane = t & 31, w = t >> 5;
    int i = blk * SCAN_CHUNK + t;
    int v = (i < NN) ? g_deg[i] : 0;
    if (i < NN) g_dinv[i] = rsqrtf((float)(v + 1));  // +1 self-loop
    int x = v;
    #pragma unroll
    for (int off = 1; off < 32; off <<= 1) {
        int y = __shfl_up_sync(0xffffffffu, x, off);
        if (lane >= off) x += y;
    }
    if (lane == 31) warpsum[w] = x;
    __syncthreads();
    if (w == 0) {
        int s = warpsum[lane];
        #pragma unroll
        for (int off = 1; off < 32; off <<= 1) {
            int y = __shfl_up_sync(0xffffffffu, s, off);
            if (lane >= off) s += y;
        }
        warpsum[lane] = s;
    }
    __syncthreads();
    int excl = x - v + (w > 0 ? warpsum[w - 1] : 0);
    if (i < NN) g_rowptr[i] = excl;               // local exclusive
    if (t == SCAN_CHUNK - 1) g_blocksum[blk] = excl + v;
}

// phase 2: one block scans the SCAN_NB block sums (exclusive) + total
__global__ void scan_block_kernel() {
    __shared__ int warpsum[32];
    int t = threadIdx.x, lane = t & 31, w = t >> 5;   // 64 threads, 2 warps
    int v = (t < SCAN_NB) ? g_blocksum[t] : 0;
    int x = v;
    #pragma unroll
    for (int off = 1; off < 32; off <<= 1) {
        int y = __shfl_up_sync(0xffffffffu, x, off);
        if (lane >= off) x += y;
    }
    if (lane == 31) warpsum[w] = x;
    __syncthreads();
    int excl = x - v + (w > 0 ? warpsum[0] : 0);
    if (t < SCAN_NB) g_blockoff[t] = excl;
    if (t == SCAN_NB - 1) g_rowptr[NN] = excl + v;  // grand total
}

// phase 3: add block offsets
__global__ void scan_add_kernel() {
    int i = blockIdx.x * blockDim.x + threadIdx.x;
    if (i < NN) g_rowptr[i] += g_blockoff[i >> 10];
}

// 4 edges per thread via int4
__global__ void csr_fill_kernel(const int* __restrict__ src, const int* __restrict__ dst) {
    int e4 = blockIdx.x * blockDim.x + threadIdx.x;
    if (e4 < NE / 4) {
        int4 s = ((const int4*)src)[e4];
        int4 d = ((const int4*)dst)[e4];
        int p;
        p = atomicAdd(&g_cursor[d.x], 1); g_col[g_rowptr[d.x] + p] = s.x;
        p = atomicAdd(&g_cursor[d.y], 1); g_col[g_rowptr[d.y] + p] = s.y;
        p = atomicAdd(&g_cursor[d.z], 1); g_col[g_rowptr[d.z] + p] = s.z;
        p = atomicAdd(&g_cursor[d.w], 1); g_col[g_rowptr[d.w] + p] = s.w;
    }
}

// ---------------- graph starts via binary search (batch is sorted) ----------
__global__ void gstart_kernel(const int* __restrict__ batch) {
    int g = blockIdx.x * blockDim.x + threadIdx.x;
    if (g > NG) return;
    if (g == NG) { g_gstart[NG] = NN; return; }
    int lo = 0, hi = NN;            // lower_bound(batch, g)
    while (lo < hi) {
        int mid = (lo + hi) >> 1;
        if (batch[mid] < g) lo = mid + 1; else hi = mid;
    }
    g_gstart[g] = lo;
}

// ---------------- aggregation: out[i] = sum_{s->i} dinv_s*dinv_i*X[s] + dinv_i^2*X[i]
// one warp per destination node; each lane owns VEC consecutive features
template <int F, int VEC, size_t XO, size_t OO>
__global__ void agg_kernel(const float* __restrict__ Xext,
                           const float* __restrict__ bias, int do_relu) {
    int warp = (blockIdx.x * blockDim.x + threadIdx.x) >> 5;
    int lane = threadIdx.x & 31;
    if (warp >= NN) return;
    constexpr int NV = F / VEC;  // active lanes

    const float* X = Xext ? Xext : (g_scratch + XO);
    float* out = g_scratch + OO;

    float acc[VEC];
    #pragma unroll
    for (int v = 0; v < VEC; v++) acc[v] = 0.0f;

    float di = g_dinv[warp];
    int b = g_rowptr[warp];
    int e = g_rowptr[warp + 1];

    if (lane < NV) {  // self-loop term
        float w = di * di;
        const float* xr = X + (size_t)warp * F + lane * VEC;
        if (VEC == 4) {
            float4 xv = *(const float4*)xr;
            acc[0] += w * xv.x; acc[1] += w * xv.y; acc[2] += w * xv.z; acc[3] += w * xv.w;
        } else if (VEC == 2) {
            float2 xv = *(const float2*)xr;
            acc[0] += w * xv.x; acc[1] += w * xv.y;
        } else {
            acc[0] += w * xr[0];
        }
    }
    // software-pipelined edge loop (prefetch col + dinv)
    int sNext = (b < e) ? g_col[b] : 0;
    float dNext = (b < e) ? g_dinv[sNext] : 0.0f;
    for (int j = b; j < e; j++) {
        int s = sNext;
        float ds = dNext;
        int jn = j + 1;
        if (jn < e) { sNext = g_col[jn]; dNext = g_dinv[sNext]; }
        float w = di * ds;
        if (lane < NV) {
            const float* xr = X + (size_t)s * F + lane * VEC;
            if (VEC == 4) {
                float4 xv = *(const float4*)xr;
                acc[0] += w * xv.x; acc[1] += w * xv.y; acc[2] += w * xv.z; acc[3] += w * xv.w;
            } else if (VEC == 2) {
                float2 xv = *(const float2*)xr;
                acc[0] += w * xv.x; acc[1] += w * xv.y;
            } else {
                acc[0] += w * xr[0];
            }
        }
    }
    if (lane < NV) {
        #pragma unroll
        for (int v = 0; v < VEC; v++) {
            float r = acc[v] + (bias ? bias[lane * VEC + v] : 0.0f);
            if (do_relu) r = fmaxf(r, 0.0f);
            acc[v] = r;
        }
        float* o = out + (size_t)warp * F + lane * VEC;
        if (VEC == 4)      *(float4*)o = make_float4(acc[0], acc[1], acc[2], acc[3]);
        else if (VEC == 2) *(float2*)o = make_float2(acc[0], acc[1]);
        else               o[0] = acc[0];
    }
}

// ---------------- SGEMM 128x128, 8x8 microtile (layer 1 only: K=30) ---------
template <size_t AO, size_t CO, bool BIAS_RELU>
__global__ void sgemm128_kernel(const float* __restrict__ B,
                                const float* __restrict__ bias,
                                int M, int N, int K) {
    constexpr int BM = 128, BN = 128, BK = 16;
    __shared__ float sA[BM][BK + 1];   // row-major, +1 pad
    __shared__ float sB[BK][BN];
    const float* A = g_scratch + AO;
    float* C = g_scratch + CO;

    int t = threadIdx.x;
    int tx = t % 16, ty = t / 16;
    int rowBase = blockIdx.y * BM;
    int colBase = blockIdx.x * BN;

    float acc[8][8] = {};

    int nk = (K + BK - 1) / BK;
    for (int kt = 0; kt < nk; kt++) {
        int k0 = kt * BK;
        #pragma unroll
        for (int i = 0; i < 8; i++) {
            int id = t + i * 256;
            int r = id / BK, c = id % BK;
            int gr = rowBase + r;
            sA[r][c] = (gr < M && k0 + c < K) ? A[(size_t)gr * K + k0 + c] : 0.0f;
        }
        #pragma unroll
        for (int i = 0; i < 8; i++) {
            int id = t + i * 256;
            int r = id / BN, c = id % BN;
            sB[r][c] = (k0 + r < K) ? B[(size_t)(k0 + r) * N + colBase + c] : 0.0f;
        }
        __syncthreads();
        #pragma unroll
        for (int k = 0; k < BK; k++) {
            float a[8];
            #pragma unroll
            for (int m = 0; m < 8; m++) a[m] = sA[ty * 8 + m][k];
            float4 b0 = *(const float4*)&sB[k][tx * 4];
            float4 b1 = *(const float4*)&sB[k][64 + tx * 4];
            float b[8] = {b0.x, b0.y, b0.z, b0.w, b1.x, b1.y, b1.z, b1.w};
            #pragma unroll
            for (int m = 0; m < 8; m++)
                #pragma unroll
                for (int n = 0; n < 8; n++) acc[m][n] += a[m] * b[n];
        }
        __syncthreads();
    }

    float bv[8];
    if (BIAS_RELU) {
        #pragma unroll
        for (int n = 0; n < 4; n++) bv[n] = bias[colBase + tx * 4 + n];
        #pragma unroll
        for (int n = 0; n < 4; n++) bv[4 + n] = bias[colBase + 64 + tx * 4 + n];
    }
    #pragma unroll
    for (int m = 0; m < 8; m++) {
        int r = rowBase + ty * 8 + m;
        if (r < M) {
            float v[8];
            #pragma unroll
            for (int n = 0; n < 8; n++) {
                v[n] = acc[m][n];
                if (BIAS_RELU) v[n] = fmaxf(v[n] + bv[n], 0.0f);
            }
            *(float4*)&C[(size_t)r * N + colBase + tx * 4] =
                make_float4(v[0], v[1], v[2], v[3]);
            *(float4*)&C[(size_t)r * N + colBase + 64 + tx * 4] =
                make_float4(v[4], v[5], v[6], v[7]);
        }
    }
}

// ---------------- tensor-core GEMM (bf16x3 split, fp32 accurate) ------------
// C[M,N] = A[M,K] @ B[K,N]; A,B,C fp32. Each operand split a = hi + lo (bf16);
// computes hi*hi + hi*lo + lo*hi via mma.sync.m16n8k16.bf16 -> rel err ~2^-16.
__device__ __forceinline__ void mma_bf16(float* c,
    uint32_t a0, uint32_t a1, uint32_t a2, uint32_t a3,
    uint32_t b0, uint32_t b1) {
    asm volatile(
        "mma.sync.aligned.m16n8k16.row.col.f32.bf16.bf16.f32 "
        "{%0,%1,%2,%3}, {%4,%5,%6,%7}, {%8,%9}, {%0,%1,%2,%3};\n"
        : "+f"(c[0]), "+f"(c[1]), "+f"(c[2]), "+f"(c[3])
        : "r"(a0), "r"(a1), "r"(a2), "r"(a3), "r"(b0), "r"(b1));
}

template <size_t AO, size_t CO, int BN>
__global__ void mma_gemm_kernel(const float* __restrict__ Bw, int M, int N, int K) {
    constexpr int BM = 128, BK = 32, SK = BK + 8;  // stride 40 bf16: conflict-free frag reads
    constexpr int WROWS = (BN == 128) ? 2 : 4;
    constexpr int WCOLS = 8 / WROWS;
    constexpr int WM = BM / WROWS;      // 64 or 32
    constexpr int WN = BN / WCOLS;      // 32
    constexpr int MT = WM / 16, NT = WN / 8;

    __shared__ __nv_bfloat16 sAhi[BM][SK];
    __shared__ __nv_bfloat16 sAlo[BM][SK];
    __shared__ __nv_bfloat16 sBhi[BN][SK];
    __shared__ __nv_bfloat16 sBlo[BN][SK];

    const float* A = g_scratch + AO;
    float* C = g_scratch + CO;
    int tid = threadIdx.x;                       // 256 threads, 8 warps
    int wid = tid >> 5, lane = tid & 31;
    int grp = lane >> 2, t4 = lane & 3;
    int warpRow = (wid % WROWS) * WM;
    int warpCol = (wid / WROWS) * WN;
    int rowBase = blockIdx.y * BM;
    int colBase = blockIdx.x * BN;

    float acc[MT][NT][4] = {};

    for (int k0 = 0; k0 < K; k0 += BK) {
        // A tile [BM x BK] fp32 -> hi/lo bf16 (4 float4 per thread)
        #pragma unroll
        for (int i = 0; i < (BM * BK / 4) / 256; i++) {
            int id = tid + i * 256;
            int r = id >> 3;                  // BK/4 = 8 float4 per row
            int kc = (id & 7) * 4;
            int gr = rowBase + r;
            float4 v = (gr < M) ? *(const float4*)&A[(size_t)gr * K + k0 + kc]
                                : make_float4(0.f, 0.f, 0.f, 0.f);
            __nv_bfloat16 hx = __float2bfloat16(v.x), hy = __float2bfloat16(v.y);
            __nv_bfloat16 hz = __float2bfloat16(v.z), hw = __float2bfloat16(v.w);
            __nv_bfloat16 lx = __float2bfloat16(v.x - __bfloat162float(hx));
            __nv_bfloat16 ly = __float2bfloat16(v.y - __bfloat162float(hy));
            __nv_bfloat16 lz = __float2bfloat16(v.z - __bfloat162float(hz));
            __nv_bfloat16 lw = __float2bfloat16(v.w - __bfloat162float(hw));
            *(__nv_bfloat162*)&sAhi[r][kc]     = __halves2bfloat162(hx, hy);
            *(__nv_bfloat162*)&sAhi[r][kc + 2] = __halves2bfloat162(hz, hw);
            *(__nv_bfloat162*)&sAlo[r][kc]     = __halves2bfloat162(lx, ly);
            *(__nv_bfloat162*)&sAlo[r][kc + 2] = __halves2bfloat162(lz, lw);
        }
        // B tile [BK x BN] fp32 -> transposed hi/lo bf16 sB[n][k]
        #pragma unroll
        for (int i = 0; i < (BK * BN) / 256; i++) {
            int id = tid + i * 256;
            int kr = id / BN;
            int n = id % BN;
            float v = Bw[(size_t)(k0 + kr) * N + colBase + n];
            __nv_bfloat16 h = __float2bfloat16(v);
            sBhi[n][kr] = h;
            sBlo[n][kr] = __float2bfloat16(v - __bfloat162float(h));
        }
        __syncthreads();

        #pragma unroll
        for (int ks = 0; ks < 2; ks++) {
            int kk = ks * 16 + t4 * 2;
            uint32_t bh[NT][2], bl[NT][2];
            #pragma unroll
            for (int ni = 0; ni < NT; ni++) {
                int n = warpCol + ni * 8 + grp;
                bh[ni][0] = *(const uint32_t*)&sBhi[n][kk];
                bh[ni][1] = *(const uint32_t*)&sBhi[n][kk + 8];
                bl[ni][0] = *(const uint32_t*)&sBlo[n][kk];
                bl[ni][1] = *(const uint32_t*)&sBlo[n][kk + 8];
            }
            #pragma unroll
            for (int mi = 0; mi < MT; mi++) {
                int r0 = warpRow + mi * 16 + grp;
                uint32_t ah0 = *(const uint32_t*)&sAhi[r0][kk];
                uint32_t ah1 = *(const uint32_t*)&sAhi[r0 + 8][kk];
                uint32_t ah2 = *(const uint32_t*)&sAhi[r0][kk + 8];
                uint32_t ah3 = *(const uint32_t*)&sAhi[r0 + 8][kk + 8];
                uint32_t al0 = *(const uint32_t*)&sAlo[r0][kk];
                uint32_t al1 = *(const uint32_t*)&sAlo[r0 + 8][kk];
                uint32_t al2 = *(const uint32_t*)&sAlo[r0][kk + 8];
                uint32_t al3 = *(const uint32_t*)&sAlo[r0 + 8][kk + 8];
                #pragma unroll
                for (int ni = 0; ni < NT; ni++) {
                    float* c = acc[mi][ni];
                    mma_bf16(c, ah0, ah1, ah2, ah3, bh[ni][0], bh[ni][1]);  // hi*hi
                    mma_bf16(c, ah0, ah1, ah2, ah3, bl[ni][0], bl[ni][1]);  // hi*lo
                    mma_bf16(c, al0, al1, al2, al3, bh[ni][0], bh[ni][1]);  // lo*hi
                }
            }
        }
        __syncthreads();
    }

    // epilogue: c0=C[g][t*2], c1=+1, c2=C[g+8][t*2], c3=+1
    #pragma unroll
    for (int mi = 0; mi < MT; mi++) {
        int r0 = rowBase + warpRow + mi * 16 + grp;
        #pragma unroll
        for (int ni = 0; ni < NT; ni++) {
            int n0 = colBase + warpCol + ni * 8 + t4 * 2;
            if (r0 < M)
                *(float2*)&C[(size_t)r0 * N + n0] =
                    make_float2(acc[mi][ni][0], acc[mi][ni][1]);
            if (r0 + 8 < M)
                *(float2*)&C[(size_t)(r0 + 8) * N + n0] =
                    make_float2(acc[mi][ni][2], acc[mi][ni][3]);
        }
    }
}

// ---------------- pooling ---------------------------------------------------
__global__ void pool_kernel() {  // one block per graph, 256 threads
    int g = blockIdx.x;
    int beg = g_gstart[g], end = g_gstart[g + 1];
    int sub = threadIdx.x >> 6, f = threadIdx.x & 63;
    float acc = 0.0f;
    for (int i = beg + sub; i < end; i += 4)
        acc += g_scratch[O_H3 + (size_t)i * F3 + f];
    __shared__ float red[256];
    red[threadIdx.x] = acc;
    __syncthreads();
    if (sub == 0)
        g_pool[g * F3 + f] = red[f] + red[64 + f] + red[128 + f] + red[192 + f];
}

// ---------------- head: logits, sigmoid, BCE loss ---------------------------
__global__ void final_kernel(const float* __restrict__ Wl, const float* __restrict__ bl,
                             const int* __restrict__ targets, float* __restrict__ out) {
    __shared__ float red[NG];
    int g = threadIdx.x;
    float c = fmaxf((float)(g_gstart[g + 1] - g_gstart[g]), 1.0f);
    float z = bl[0];
    #pragma unroll
    for (int f = 0; f < F3; f++) z += (g_pool[g * F3 + f] / c) * Wl[f];
    out[g] = 1.0f / (1.0f + expf(-z));
    float y = (float)targets[g];
    red[g] = fmaxf(z, 0.0f) + log1pf(expf(-fabsf(z))) - z * y;
    __syncthreads();
    for (int s = NG / 2; s > 0; s >>= 1) {
        if (g < s) red[g] += red[g + s];
        __syncthreads();
    }
    if (g == 0) out[NG] = red[0] / (float)NG;
}

// ---------------- launch ----------------------------------------------------
extern "C" void kernel_launch(void* const* d_in, const int* in_sizes, int n_in,
                              void* d_out, int out_size) {
    const float* x       = (const float*)d_in[0];   // [N,30]
    const int*   eidx    = (const int*)d_in[1];     // [2,E]
    const int*   batch   = (const int*)d_in[2];     // [N] sorted
    const int*   targets = (const int*)d_in[3];     // [G]
    const float* W1 = (const float*)d_in[4];
    const float* b1 = (const float*)d_in[5];
    const float* W2 = (const float*)d_in[6];
    const float* b2 = (const float*)d_in[7];
    const float* W3 = (const float*)d_in[8];
    const float* b3 = (const float*)d_in[9];
    const float* Wl = (const float*)d_in[10];
    const float* bl = (const float*)d_in[11];
    float* out = (float*)d_out;

    const int* src = eidx;       // edge_index[0]
    const int* dst = eidx + NE;  // edge_index[1]

    const int TB = 256;
    int nb_nodes = (NN + TB - 1) / TB;
    int nb_edges4 = (NE / 4 + TB - 1) / TB;

    // graph preprocessing (recomputed every call; deterministic)
    zero_kernel<<<nb_nodes, TB>>>();
    deg_kernel<<<nb_edges4, TB>>>(dst);
    scan_local_kernel<<<SCAN_NB, SCAN_CHUNK>>>();   // also writes g_dinv
    scan_block_kernel<<<1, 64>>>();
    scan_add_kernel<<<nb_nodes, TB>>>();
    csr_fill_kernel<<<nb_edges4, TB>>>(src, dst);
    gstart_kernel<<<(NG + 1 + TB - 1) / TB, TB>>>(batch);

    int agg_blocks = (NN * 32 + TB - 1) / TB;  // one warp per node
    int mRows = (NN + 127) / 128;

    // layer 1: aggregate 30-dim input, then SIMT GEMM 30->256 (+b1, relu)
    agg_kernel<F0, 1, 0, O_AGG0><<<agg_blocks, TB>>>(x, nullptr, 0);
    {
        dim3 grid(F1 / 128, mRows);
        sgemm128_kernel<O_AGG0, O_H1, true><<<grid, 256>>>(W1, b1, NN, F1, F0);
    }

    // layer 2: tensor GEMM 256->128, aggregate, +b2, relu
    {
        dim3 grid(F2 / 128, mRows);
        mma_gemm_kernel<O_H1, O_T2, 128><<<grid, 256>>>(W2, NN, F2, F1);
    }
    agg_kernel<F2, 4, O_T2, O_H2><<<agg_blocks, TB>>>(nullptr, b2, 1);

    // layer 3: tensor GEMM 128->64, aggregate, +b3 (no relu)
    {
        dim3 grid(F3 / 64, mRows);
        mma_gemm_kernel<O_H2, O_T3, 64><<<grid, 256>>>(W3, NN, F3, F2);
    }
    agg_kernel<F3, 2, O_T3, O_H3><<<agg_blocks, TB>>>(nullptr, b3, 0);

    // global mean pool + head
    pool_kernel<<<NG, 256>>>();
    final_kernel<<<1, NG>>>(Wl, bl, targets, out);
    (void)in_sizes; (void)n_in; (void)out_size;
}